// round 6
// baseline (speedup 1.0000x reference)
#include <cuda_runtime.h>
#include <cuda_bf16.h>

// Problem constants
#define E_DIM 1024
#define B_DIM 32
#define S_DIM 1024
#define NROWS (B_DIM * S_DIM)   // 32768 rows of length E

// Scratch for the 3-stage GEMV chain (B x E each). __device__ globals: no allocation.
__device__ float g_t1[B_DIM * E_DIM];   // proj_heat
__device__ float g_t2[B_DIM * E_DIM];   // v
__device__ float g_a [B_DIM * E_DIM];   // attn_out per batch (broadcast over S)

// y[b,e] = sum_k x[b,k] * W[e,k] + bias[e]
// grid: (B, E/4), block: 128 (4 warps, one output e per warp).
// blockIdx.x (batch) is fastest -> the 32 blocks sharing one e-group run
// nearly concurrently, so W rows hit L2/L1 instead of re-reading DRAM.
__global__ __launch_bounds__(128) void gemv_kernel(
    const float* __restrict__ x,
    const float* __restrict__ W,
    const float* __restrict__ bias,
    float* __restrict__ y)
{
    const int b    = blockIdx.x;
    const int warp = threadIdx.x >> 5;
    const int lane = threadIdx.x & 31;
    const int e    = blockIdx.y * 4 + warp;

    const float4* __restrict__ xr = (const float4*)(x + (size_t)b * E_DIM);
    const float4* __restrict__ wr = (const float4*)(W + (size_t)e * E_DIM);

    float acc = 0.0f;
#pragma unroll
    for (int i = 0; i < 8; i++) {
        float4 xv = xr[lane + 32 * i];
        float4 wv = wr[lane + 32 * i];
        acc += xv.x * wv.x + xv.y * wv.y + xv.z * wv.z + xv.w * wv.w;
    }
#pragma unroll
    for (int off = 16; off; off >>= 1)
        acc += __shfl_xor_sync(0xFFFFFFFFu, acc, off);

    if (lane == 0)
        y[(size_t)b * E_DIM + e] = acc + bias[e];
}

// out[b,s,:] = LayerNorm(img[b,s,:] + a[b,:]) * gamma + beta
// Warp-per-row, row (1024 floats) held in registers: 8x LDG.128 per lane,
// shuffle-only reductions, no shared memory, no block barrier.
__global__ __launch_bounds__(256) void add_ln_kernel(
    const float* __restrict__ img,
    const float* __restrict__ a,
    const float* __restrict__ gamma,
    const float* __restrict__ beta,
    float* __restrict__ out)
{
    const int warp = threadIdx.x >> 5;
    const int lane = threadIdx.x & 31;
    const int r = blockIdx.x * 8 + warp;      // 0 .. 32767
    const int b = r >> 10;                    // r / S

    const float4* __restrict__ xr = (const float4*)(img + (size_t)r * E_DIM);
    const float4* __restrict__ ar = (const float4*)(a   + (size_t)b * E_DIM);

    float4 v[8];
    float s = 0.0f;
#pragma unroll
    for (int i = 0; i < 8; i++) {
        float4 xv = xr[lane + 32 * i];
        float4 av = ar[lane + 32 * i];     // 4KB per batch, L1-resident
        xv.x += av.x; xv.y += av.y; xv.z += av.z; xv.w += av.w;
        v[i] = xv;
        s += xv.x + xv.y + xv.z + xv.w;
    }
#pragma unroll
    for (int off = 16; off; off >>= 1)
        s += __shfl_xor_sync(0xFFFFFFFFu, s, off);
    const float mu = s * (1.0f / (float)E_DIM);

    float ss = 0.0f;
#pragma unroll
    for (int i = 0; i < 8; i++) {
        float dx = v[i].x - mu, dy = v[i].y - mu;
        float dz = v[i].z - mu, dw = v[i].w - mu;
        ss += dx * dx + dy * dy + dz * dz + dw * dw;
    }
#pragma unroll
    for (int off = 16; off; off >>= 1)
        ss += __shfl_xor_sync(0xFFFFFFFFu, ss, off);
    const float rinv = rsqrtf(ss * (1.0f / (float)E_DIM) + 1e-5f);

    float4* __restrict__ orow = (float4*)(out + (size_t)r * E_DIM);
    const float4* __restrict__ g4 = (const float4*)gamma;
    const float4* __restrict__ b4 = (const float4*)beta;
#pragma unroll
    for (int i = 0; i < 8; i++) {
        float4 gv = g4[lane + 32 * i];
        float4 bv = b4[lane + 32 * i];
        float4 o;
        o.x = (v[i].x - mu) * rinv * gv.x + bv.x;
        o.y = (v[i].y - mu) * rinv * gv.y + bv.y;
        o.z = (v[i].z - mu) * rinv * gv.z + bv.z;
        o.w = (v[i].w - mu) * rinv * gv.w + bv.w;
        orow[lane + 32 * i] = o;
    }
}

// Input order (metadata): 0 img_feat, 1 heat_feat, 2 W_img, 3 b_img,
// 4 W_heat, 5 b_heat, 6 Wq, 7 bq, 8 Wk, 9 bk, 10 Wv, 11 bv,
// 12 Wo, 13 bo, 14 gamma, 15 beta.
// softmax over KV-len==1 == 1.0, so q/W_img/Wq branches are dead code.
extern "C" void kernel_launch(void* const* d_in, const int* in_sizes, int n_in,
                              void* d_out, int out_size)
{
    const float* img_feat  = (const float*)d_in[0];
    const float* heat_feat = (const float*)d_in[1];
    const float* W_heat    = (const float*)d_in[4];
    const float* b_heat    = (const float*)d_in[5];
    const float* Wv        = (const float*)d_in[10];
    const float* bv        = (const float*)d_in[11];
    const float* Wo        = (const float*)d_in[12];
    const float* bo        = (const float*)d_in[13];
    const float* gamma     = (const float*)d_in[14];
    const float* beta      = (const float*)d_in[15];
    float* out = (float*)d_out;

    float *t1, *t2, *a;
    cudaGetSymbolAddress((void**)&t1, g_t1);
    cudaGetSymbolAddress((void**)&t2, g_t2);
    cudaGetSymbolAddress((void**)&a,  g_a);

    dim3 ggrid(B_DIM, E_DIM / 4);
    // proj_heat = heat @ W_heat^T + b_heat
    gemv_kernel<<<ggrid, 128>>>(heat_feat, W_heat, b_heat, t1);
    // v = proj_heat @ Wv^T + bv
    gemv_kernel<<<ggrid, 128>>>(t1, Wv, bv, t2);
    // a = v @ Wo^T + bo   (== attn_out for every s)
    gemv_kernel<<<ggrid, 128>>>(t2, Wo, bo, a);
    // out = LN(img + a[b]) * gamma + beta
    add_ln_kernel<<<NROWS / 8, 256>>>(img_feat, a, gamma, beta, out);
}